// round 3
// baseline (speedup 1.0000x reference)
#include <cuda_runtime.h>
#include <math.h>

#define NS    100   // stocks
#define DDAYS 20    // days
#define TTXT  30    // texts per day
#define HH    64    // hidden
#define G3    192   // 3*H
#define NHEADS 8
#define FTXT  512
#define FPRC  3

// ---------------- scratch (device globals; no allocation allowed) ----------------
__device__ float g_gi_text[(size_t)NS * DDAYS * TTXT * G3];   // 11.52M floats
__device__ float g_news[NS * DDAYS * HH];
__device__ float g_price_vec[NS * HH];
__device__ float g_text_vec[NS * HH];
__device__ float g_feature[NS * HH];
__device__ float g_xcat[NS * NHEADS * HH];

__device__ __forceinline__ float sigm(float x) { return 1.f / (1.f + expf(-x)); }

// =====================================================================
// Kernel A: text-GRU input projection
//   gi[s,d,t,g] = text[s,d,t,:] . tg_Wih[s,g,:] + tg_bih[s,g]
// One block per (s,d); 192 threads (one per gate row g); x tiled in smem,
// broadcast via float4 LDS so FMA:LDS ratio is 4:1.
// =====================================================================
__global__ void __launch_bounds__(192) text_gi_kernel(
    const float* __restrict__ X, const float* __restrict__ Wih,
    const float* __restrict__ bih)
{
    __shared__ __align__(16) float xt[32 * 32];   // [kk][t], row stride 32
    int b = blockIdx.x;           // s*DDAYS + d
    int s = b / DDAYS;
    int g = threadIdx.x;
    const float* xg = X + (size_t)b * TTXT * FTXT;
    const float* wg = Wih + ((size_t)s * G3 + g) * FTXT;

    float acc[32];
#pragma unroll
    for (int t = 0; t < 32; t++) acc[t] = 0.f;
    // zero the two padding t-rows once (never rewritten)
    if (g < 64) { int kk = g & 31, t = 30 + (g >> 5); xt[kk * 32 + t] = 0.f; }

    for (int k0 = 0; k0 < FTXT; k0 += 32) {
        __syncthreads();
        for (int idx = threadIdx.x; idx < TTXT * 32; idx += 192) {
            int t = idx >> 5, kk = idx & 31;
            xt[kk * 32 + t] = xg[t * FTXT + k0 + kk];   // coalesced over kk
        }
        __syncthreads();
#pragma unroll
        for (int kk4 = 0; kk4 < 8; kk4++) {
            float4 wv = *(const float4*)(wg + k0 + kk4 * 4);
#pragma unroll
            for (int u = 0; u < 4; u++) {
                float w = (u == 0) ? wv.x : (u == 1) ? wv.y : (u == 2) ? wv.z : wv.w;
                const float4* xrow = (const float4*)(xt + (kk4 * 4 + u) * 32);
#pragma unroll
                for (int t4 = 0; t4 < 8; t4++) {
                    float4 xv = xrow[t4];                 // 16B smem broadcast
                    acc[t4 * 4 + 0] += w * xv.x;
                    acc[t4 * 4 + 1] += w * xv.y;
                    acc[t4 * 4 + 2] += w * xv.z;
                    acc[t4 * 4 + 3] += w * xv.w;
                }
            }
        }
    }
    float bg = bih[s * G3 + g];
    float* out = g_gi_text + (size_t)b * TTXT * G3;
#pragma unroll
    for (int t = 0; t < TTXT; t++) out[t * G3 + g] = acc[t] + bg;
}

// =====================================================================
// Generic GRU stage + attention pooling (torch GRU semantics, h0=0).
// 192 threads. Each thread holds its Whh row in 64 registers.
// FIN>0: compute gi inline from X [batch,TSEQ,FIN]; FIN==0: gi precomputed.
// out[b,:] = attn_pool(outs, h_last, Wa[s])
// =====================================================================
template <int TSEQ, int FIN>
__global__ void __launch_bounds__(192) gru_stage_kernel(
    const float* __restrict__ X, const float* __restrict__ GI,
    const float* __restrict__ Wih, const float* __restrict__ Whh,
    const float* __restrict__ bih, const float* __restrict__ bhh,
    const float* __restrict__ Wa, float* __restrict__ out, int day_div)
{
    __shared__ __align__(16) float h[64];
    __shared__ float gh[192];
    __shared__ __align__(16) float outs[TSEQ * 64];
    __shared__ float att[32];
    __shared__ float score[32];
    __shared__ float gi_s[(FIN > 0) ? TSEQ * G3 : 1];
    __shared__ float xs[(FIN > 0) ? TSEQ * FIN : 1];

    int b = blockIdx.x;
    int s = b / day_div;
    int tid = threadIdx.x;

    // Whh row of this thread -> registers (fully unrolled constant indexing)
    float4 w4[16];
    const float4* wp = (const float4*)(Whh + ((size_t)s * G3 + tid) * 64);
#pragma unroll
    for (int i = 0; i < 16; i++) w4[i] = wp[i];
    float bh = bhh[s * G3 + tid];

    const float* gi;
    if (FIN > 0) {
        for (int idx = tid; idx < TSEQ * FIN; idx += 192)
            xs[idx] = X[(size_t)b * TSEQ * FIN + idx];
        __syncthreads();
        float bg = bih[s * G3 + tid];
        const float* wgp = Wih + ((size_t)s * G3 + tid) * FIN;
        for (int t = 0; t < TSEQ; t++) {
            float a = bg;
#pragma unroll 4
            for (int k = 0; k < FIN; k++) a += wgp[k] * xs[t * FIN + k];
            gi_s[t * G3 + tid] = a;
        }
        gi = gi_s;
    } else {
        gi = GI + (size_t)b * TSEQ * G3;
    }
    if (tid < 64) h[tid] = 0.f;
    __syncthreads();

    for (int t = 0; t < TSEQ; t++) {
        float a = bh;
        const float4* h4 = (const float4*)h;
#pragma unroll
        for (int i = 0; i < 16; i++) {
            float4 hv = h4[i];
            a += w4[i].x * hv.x + w4[i].y * hv.y + w4[i].z * hv.z + w4[i].w * hv.w;
        }
        gh[tid] = a;
        __syncthreads();
        if (tid < 64) {
            const float* gt = gi + t * G3;
            float r = sigm(gt[tid] + gh[tid]);
            float z = sigm(gt[64 + tid] + gh[64 + tid]);
            float n = tanhf(gt[128 + tid] + r * gh[128 + tid]);
            float hn = (1.f - z) * n + z * h[tid];
            h[tid] = hn;
            outs[t * 64 + tid] = hn;
        }
        __syncthreads();
    }

    // attention pool:  score_t = tanh(outs_t @ Wa) . h_last
    const float* WaS = Wa + (size_t)s * 64 * 64;
    int warp = tid >> 5, lane = tid & 31;
    for (int t = warp; t < TSEQ; t += 6) {
        float q1 = 0.f, q2 = 0.f;
        for (int i = 0; i < 64; i++) {
            float o = outs[t * 64 + i];
            q1 += o * WaS[i * 64 + lane];
            q2 += o * WaS[i * 64 + lane + 32];
        }
        float sc = tanhf(q1) * h[lane] + tanhf(q2) * h[lane + 32];
#pragma unroll
        for (int off = 16; off > 0; off >>= 1)
            sc += __shfl_xor_sync(0xffffffffu, sc, off);
        if (lane == 0) score[t] = sc;
    }
    __syncthreads();
    if (tid < 32) {
        float v = (tid < TSEQ) ? score[tid] : -1e30f;
        float m = v;
#pragma unroll
        for (int off = 16; off > 0; off >>= 1)
            m = fmaxf(m, __shfl_xor_sync(0xffffffffu, m, off));
        float e = (tid < TSEQ) ? expf(v - m) : 0.f;
        float ss = e;
#pragma unroll
        for (int off = 16; off > 0; off >>= 1)
            ss += __shfl_xor_sync(0xffffffffu, ss, off);
        att[tid] = e / ss;
    }
    __syncthreads();
    if (tid < 64) {
        float a = 0.f;
#pragma unroll 2
        for (int t = 0; t < TSEQ; t++) a += att[t] * outs[t * 64 + tid];
        out[(size_t)b * 64 + tid] = a;
    }
}

// =====================================================================
// Bilinear fusion: feature[s,o] = tanh( sum_ij text[i] B[s,o,i,j] price[j] + b )
// 100 blocks x 512 threads; thread = (o, j-chunk of 8). Memory-bound (100MB).
// =====================================================================
__global__ void __launch_bounds__(512) bilinear_kernel(
    const float* __restrict__ B, const float* __restrict__ bb)
{
    __shared__ float pr_s[64], tx_s[64];
    int sidx = blockIdx.x;
    int tid = threadIdx.x;
    if (tid < 64) pr_s[tid] = g_price_vec[sidx * 64 + tid];
    else if (tid < 128) tx_s[tid - 64] = g_text_vec[sidx * 64 + tid - 64];
    __syncthreads();
    int o = tid >> 3, q = tid & 7;
    float pr[8];
#pragma unroll
    for (int j = 0; j < 8; j++) pr[j] = pr_s[q * 8 + j];
    const float* Bp = B + (((size_t)sidx * 64 + o) * 64) * 64 + q * 8;
    float acc = 0.f;
    for (int i = 0; i < 64; i++) {
        float4 v1 = *(const float4*)(Bp + (size_t)i * 64);
        float4 v2 = *(const float4*)(Bp + (size_t)i * 64 + 4);
        float tp = v1.x * pr[0] + v1.y * pr[1] + v1.z * pr[2] + v1.w * pr[3]
                 + v2.x * pr[4] + v2.y * pr[5] + v2.z * pr[6] + v2.w * pr[7];
        acc += tx_s[i] * tp;
    }
    acc += __shfl_xor_sync(0xffffffffu, acc, 1);
    acc += __shfl_xor_sync(0xffffffffu, acc, 2);
    acc += __shfl_xor_sync(0xffffffffu, acc, 4);
    if (q == 0) g_feature[sidx * 64 + o] = tanhf(acc + bb[sidx * 64 + o]);
}

// =====================================================================
// GAT heads (8 blocks, one per head): masked-softmax attention, elu, concat.
// =====================================================================
__global__ void __launch_bounds__(256) gat_head_kernel(
    const float* __restrict__ gatW, const float* __restrict__ gatA,
    const float* __restrict__ adj)
{
    __shared__ float hh[NS * 64];
    __shared__ float f1[NS], f2[NS];
    __shared__ float attrow[8][NS];
    int head = blockIdx.x;
    int tid = threadIdx.x;
    const float* W = gatW + head * 64 * 64;
    const float* a = gatA + head * 128;
    for (int idx = tid; idx < NS * 64; idx += 256) {
        int i = idx >> 6, k = idx & 63;
        float acc = 0.f;
        const float* xr = g_feature + i * 64;
        for (int m = 0; m < 64; m++) acc += xr[m] * W[m * 64 + k];
        hh[idx] = acc;
    }
    __syncthreads();
    if (tid < NS) {
        float s1 = 0.f, s2 = 0.f;
        for (int k = 0; k < 64; k++) {
            float hv = hh[tid * 64 + k];
            s1 += hv * a[k];
            s2 += hv * a[64 + k];
        }
        f1[tid] = s1; f2[tid] = s2;
    }
    __syncthreads();
    int warp = tid >> 5, lane = tid & 31;
    for (int i = warp; i < NS; i += 8) {
        float fi = f1[i];
        float m = -1e30f;
        for (int j = lane; j < NS; j += 32) {
            float e = fi + f2[j];
            e = (e > 0.f) ? e : 0.2f * e;
            e = (adj[i * NS + j] > 0.f) ? e : -9e15f;
            attrow[warp][j] = e;
            m = fmaxf(m, e);
        }
#pragma unroll
        for (int off = 16; off > 0; off >>= 1)
            m = fmaxf(m, __shfl_xor_sync(0xffffffffu, m, off));
        float ss = 0.f;
        for (int j = lane; j < NS; j += 32) {
            float w = expf(attrow[warp][j] - m);
            attrow[warp][j] = w;
            ss += w;
        }
#pragma unroll
        for (int off = 16; off > 0; off >>= 1)
            ss += __shfl_xor_sync(0xffffffffu, ss, off);
        float inv = 1.f / ss;
        for (int k = lane; k < 64; k += 32) {
            float acc = 0.f;
            for (int j = 0; j < NS; j++) acc += attrow[warp][j] * hh[j * 64 + k];
            float v = acc * inv;
            v = (v > 0.f) ? v : expm1f(v);               // elu
            g_xcat[i * (NHEADS * 64) + head * 64 + k] = v;
        }
    }
}

// =====================================================================
// Final: output GAT layer + blend + double softmax + loss. Single block.
// =====================================================================
__global__ void __launch_bounds__(256) final_kernel(
    const float* __restrict__ outW, const float* __restrict__ outA,
    const float* __restrict__ blW, const float* __restrict__ blb,
    const float* __restrict__ adj, const int* __restrict__ label,
    float* __restrict__ dout, int out_size)
{
    __shared__ float h2[2 * NS];
    __shared__ float o1[2 * NS];
    __shared__ float f1[NS], f2[NS];
    __shared__ float lp[NS];
    int tid = threadIdx.x;
    if (tid < 2 * NS) {
        int i = tid >> 1, c = tid & 1;
        float acc = 0.f;
        const float* xr = g_xcat + i * (NHEADS * 64);
        for (int m = 0; m < NHEADS * 64; m++) acc += xr[m] * outW[m * 2 + c];
        h2[tid] = acc;
        float a2 = blb[c];
        const float* fr = g_feature + i * 64;
        for (int k = 0; k < 64; k++) a2 += fr[k] * blW[k * 2 + c];
        o1[tid] = tanhf(a2);
    }
    __syncthreads();
    if (tid < NS) {
        f1[tid] = h2[2 * tid] * outA[0] + h2[2 * tid + 1] * outA[1];
        f2[tid] = h2[2 * tid] * outA[2] + h2[2 * tid + 1] * outA[3];
    }
    __syncthreads();
    int warp = tid >> 5, lane = tid & 31;
    for (int i = warp; i < NS; i += 8) {
        float fi = f1[i];
        float m = -1e30f;
        for (int j = lane; j < NS; j += 32) {
            float e = fi + f2[j];
            e = (e > 0.f) ? e : 0.2f * e;
            e = (adj[i * NS + j] > 0.f) ? e : -9e15f;
            m = fmaxf(m, e);
        }
#pragma unroll
        for (int off = 16; off > 0; off >>= 1)
            m = fmaxf(m, __shfl_xor_sync(0xffffffffu, m, off));
        float ss = 0.f, a0 = 0.f, a1 = 0.f;
        for (int j = lane; j < NS; j += 32) {
            float e = fi + f2[j];
            e = (e > 0.f) ? e : 0.2f * e;
            e = (adj[i * NS + j] > 0.f) ? e : -9e15f;
            float w = expf(e - m);
            ss += w; a0 += w * h2[2 * j]; a1 += w * h2[2 * j + 1];
        }
#pragma unroll
        for (int off = 16; off > 0; off >>= 1) {
            ss += __shfl_xor_sync(0xffffffffu, ss, off);
            a0 += __shfl_xor_sync(0xffffffffu, a0, off);
            a1 += __shfl_xor_sync(0xffffffffu, a1, off);
        }
        if (lane == 0) {
            float x0 = a0 / ss, x1 = a1 / ss;
            x0 = (x0 > 0.f) ? x0 : expm1f(x0);           // elu
            x1 = (x1 > 0.f) ? x1 : expm1f(x1);
            float v0 = x0 + o1[2 * i], v1 = x1 + o1[2 * i + 1];
            float mm = fmaxf(v0, v1);
            float e0 = expf(v0 - mm), e1 = expf(v1 - mm);
            float inv = 1.f / (e0 + e1);
            float p0 = e0 * inv, p1 = e1 * inv;
            int base = (out_size > 2 * NS) ? 1 : 0;
            dout[base + 2 * i] = p0;
            dout[base + 2 * i + 1] = p1;
            // loss on already-softmaxed output (double-softmax bug preserved)
            float mm2 = fmaxf(p0, p1);
            float lse = mm2 + logf(expf(p0 - mm2) + expf(p1 - mm2));
            int lb = label[i];
            lp[i] = ((lb != 0) ? p1 : p0) - lse;
        }
    }
    __syncthreads();
    if (tid == 0 && out_size > 2 * NS) {
        float sum = 0.f;
        for (int i = 0; i < NS; i++) sum += lp[i];       // deterministic order
        dout[0] = -sum / NS;
    }
}

// =====================================================================
extern "C" void kernel_launch(void* const* d_in, const int* in_sizes, int n_in,
                              void* d_out, int out_size)
{
    // dict order: text, price, label, adj, train, then 23 weight arrays.
    // Hedge: if the scalar `train` is not materialized, n_in == 27.
    int o = n_in - 23;  // index of pg_Wih (5 if train present, 4 if not)
    const float* text   = (const float*)d_in[0];
    const float* price  = (const float*)d_in[1];
    const int*   label  = (const int*)d_in[2];
    const float* adj    = (const float*)d_in[3];
    const float* pg_Wih = (const float*)d_in[o + 0];
    const float* pg_Whh = (const float*)d_in[o + 1];
    const float* pg_bih = (const float*)d_in[o + 2];
    const float* pg_bhh = (const float*)d_in[o + 3];
    const float* pa_W   = (const float*)d_in[o + 4];
    const float* tg_Wih = (const float*)d_in[o + 5];
    const float* tg_Whh = (const float*)d_in[o + 6];
    const float* tg_bih = (const float*)d_in[o + 7];
    const float* tg_bhh = (const float*)d_in[o + 8];
    const float* ta_W   = (const float*)d_in[o + 9];
    const float* sg_Wih = (const float*)d_in[o + 10];
    const float* sg_Whh = (const float*)d_in[o + 11];
    const float* sg_bih = (const float*)d_in[o + 12];
    const float* sg_bhh = (const float*)d_in[o + 13];
    const float* sa_W   = (const float*)d_in[o + 14];
    const float* bil_B  = (const float*)d_in[o + 15];
    const float* bil_b  = (const float*)d_in[o + 16];
    const float* bl_W   = (const float*)d_in[o + 17];
    const float* bl_b   = (const float*)d_in[o + 18];
    const float* gat_W  = (const float*)d_in[o + 19];
    const float* gat_a  = (const float*)d_in[o + 20];
    const float* out_W  = (const float*)d_in[o + 21];
    const float* out_a  = (const float*)d_in[o + 22];
    (void)in_sizes;

    float *gi_ptr, *news_ptr, *pvec_ptr, *tvec_ptr;
    cudaGetSymbolAddress((void**)&gi_ptr,   g_gi_text);
    cudaGetSymbolAddress((void**)&news_ptr, g_news);
    cudaGetSymbolAddress((void**)&pvec_ptr, g_price_vec);
    cudaGetSymbolAddress((void**)&tvec_ptr, g_text_vec);

    // A: text input projections  [2000 blocks]
    text_gi_kernel<<<NS * DDAYS, 192>>>(text, tg_Wih, tg_bih);
    // price encoder (independent of A/B) [100 blocks]
    gru_stage_kernel<DDAYS, FPRC><<<NS, 192>>>(
        price, nullptr, pg_Wih, pg_Whh, pg_bih, pg_bhh, pa_W, pvec_ptr, 1);
    // B: text GRU + pool per (s,d) -> news  [2000 blocks]
    gru_stage_kernel<TTXT, 0><<<NS * DDAYS, 192>>>(
        nullptr, gi_ptr, nullptr, tg_Whh, nullptr, tg_bhh, ta_W, news_ptr, DDAYS);
    // D: day-sequence GRU over news -> text_vec  [100 blocks]
    gru_stage_kernel<DDAYS, HH><<<NS, 192>>>(
        news_ptr, nullptr, sg_Wih, sg_Whh, sg_bih, sg_bhh, sa_W, tvec_ptr, 1);
    // E: bilinear fusion -> feature
    bilinear_kernel<<<NS, 512>>>(bil_B, bil_b);
    // F1: 8 GAT heads -> concat
    gat_head_kernel<<<NHEADS, 256>>>(gat_W, gat_a, adj);
    // F2: output GAT layer + blend + softmax + loss
    final_kernel<<<1, 256>>>(out_W, out_a, bl_W, bl_b, adj, label,
                             (float*)d_out, out_size);
}

// round 4
// speedup vs baseline: 1.1616x; 1.1616x over previous
#include <cuda_runtime.h>
#include <math.h>

#define NS    100   // stocks
#define DDAYS 20    // days
#define TTXT  30    // texts per day
#define HH    64    // hidden
#define G3    192   // 3*H
#define NHEADS 8
#define FTXT  512
#define FPRC  3

// ---------------- scratch (device globals; no allocation allowed) ----------------
__device__ float g_gi_text[(size_t)NS * DDAYS * TTXT * G3];   // 11.52M floats
__device__ float g_news[NS * DDAYS * HH];
__device__ float g_price_vec[NS * HH];
__device__ float g_text_vec[NS * HH];
__device__ float g_feature[NS * HH];
__device__ float g_xcat[NS * NHEADS * HH];

typedef unsigned long long ull;

// packed fp32x2 FMA (Blackwell FFMA2; PTX-only, exact fp32 semantics)
__device__ __forceinline__ ull ffma2(ull a, ull b, ull c) {
    ull d;
    asm("fma.rn.f32x2 %0, %1, %2, %3;" : "=l"(d) : "l"(a), "l"(b), "l"(c));
    return d;
}
__device__ __forceinline__ float2 unpack2(ull v) {
    float2 r;
    asm("mov.b64 {%0, %1}, %2;" : "=f"(r.x), "=f"(r.y) : "l"(v));
    return r;
}
__device__ __forceinline__ float sigm(float x) { return 1.f / (1.f + expf(-x)); }

// =====================================================================
// Kernel A: text-GRU input projection
//   gi[s,d,t,g] = text[s,d,t,:] . tg_Wih[s,g,:] + tg_bih[s,g]
// One block per (s,d); 192 threads (one per gate row g).
// x tile kept [t][k] in smem (conflict-free stores; ull2 broadcast reads);
// FFMA2 packs k-pairs -> 2 MACs/issue slot; per-t accumulator packs the
// even-k / odd-k partial sums (summed at the end).
// =====================================================================
__global__ void __launch_bounds__(192) text_gi_kernel(
    const float* __restrict__ X, const float* __restrict__ Wih,
    const float* __restrict__ bih)
{
    __shared__ __align__(16) float xt[TTXT * 32];   // [t][kk]
    int b = blockIdx.x;           // s*DDAYS + d
    int s = b / DDAYS;
    int g = threadIdx.x;
    const float* xg = X + (size_t)b * TTXT * FTXT;
    const float* wg = Wih + ((size_t)s * G3 + g) * FTXT;

    ull acc2[TTXT];
#pragma unroll
    for (int t = 0; t < TTXT; t++) acc2[t] = 0ull;

    for (int k0 = 0; k0 < FTXT; k0 += 32) {
        __syncthreads();
        for (int idx = threadIdx.x; idx < TTXT * 32; idx += 192) {
            int t = idx >> 5, kk = idx & 31;
            xt[t * 32 + kk] = xg[t * FTXT + k0 + kk];   // coalesced gmem, conflict-free smem
        }
        __syncthreads();
        ull wk[16];
        const ulonglong2* wp2 = (const ulonglong2*)(wg + k0);
#pragma unroll
        for (int i = 0; i < 8; i++) { ulonglong2 wv = wp2[i]; wk[2*i] = wv.x; wk[2*i+1] = wv.y; }
#pragma unroll
        for (int t = 0; t < TTXT; t++) {
            const ulonglong2* xr = (const ulonglong2*)(xt + t * 32);  // broadcast, no conflicts
            ull a = acc2[t];
#pragma unroll
            for (int i = 0; i < 8; i++) {
                ulonglong2 xv = xr[i];
                a = ffma2(wk[2*i],     xv.x, a);
                a = ffma2(wk[2*i + 1], xv.y, a);
            }
            acc2[t] = a;
        }
    }
    float bg = bih[s * G3 + g];
    float* out = g_gi_text + (size_t)b * TTXT * G3;
#pragma unroll
    for (int t = 0; t < TTXT; t++) {
        float2 v = unpack2(acc2[t]);
        out[t * G3 + g] = v.x + v.y + bg;
    }
}

// =====================================================================
// Generic GRU stage + attention pooling (torch GRU semantics, h0=0).
// 192 threads. Two-phase register reuse: Wih row -> regs (hi-MLP), compute
// ALL gi into smem; then Whh row -> regs; then recurrence (FFMA2 4-chain).
// Wa prefetched into smem up-front; gi prefetched (FIN==0) with float4.
// =====================================================================
template <int TSEQ, int FIN>
__device__ __forceinline__ void gru_body(
    int s, int b,
    const float* __restrict__ X, const float* __restrict__ GI,
    const float* __restrict__ Wih, const float* __restrict__ Whh,
    const float* __restrict__ bih, const float* __restrict__ bhh,
    const float* __restrict__ WaG, float* __restrict__ outv, char* smraw)
{
    float* gi    = (float*)smraw;         // TSEQ*192
    float* outs  = gi + TSEQ * G3;        // TSEQ*64
    float* wa    = outs + TSEQ * HH;      // 4096
    float* h     = wa + 4096;             // 64
    float* gh    = h + 64;                // 192
    float* score = gh + G3;               // 32
    float* att   = score + 32;            // 32
    float* xs    = att + 32;              // TSEQ*FIN (FIN>0 only)
    int tid = threadIdx.x;

    // prefetch Wa (needed only at the end; latency hidden behind recurrence)
    {
        const float4* src = (const float4*)(WaG + (size_t)s * 4096);
        float4* dst = (float4*)wa;
        for (int i = tid; i < 1024; i += 192) dst[i] = src[i];
    }

    ull w2[32];

    if (FIN > 0) {
        if (FIN == 3) {
            for (int i = tid; i < TSEQ * 3; i += 192) xs[i] = X[(size_t)b * TSEQ * 3 + i];
        } else {
            const float4* src = (const float4*)(X + (size_t)b * TSEQ * FIN);
            float4* dst = (float4*)xs;
            for (int i = tid; i < TSEQ * FIN / 4; i += 192) dst[i] = src[i];
        }
        float bg = bih[s * G3 + tid];
        if (FIN == 3) {
            const float* wr = Wih + ((size_t)s * G3 + tid) * 3;
            float wi0 = wr[0], wi1 = wr[1], wi2 = wr[2];
            __syncthreads();
            for (int t = 0; t < TSEQ; t++)
                gi[t * G3 + tid] = bg + wi0 * xs[t*3] + wi1 * xs[t*3+1] + wi2 * xs[t*3+2];
        } else {
            const ulonglong2* wp = (const ulonglong2*)(Wih + ((size_t)s * G3 + tid) * 64);
#pragma unroll
            for (int i = 0; i < 16; i++) { ulonglong2 v = wp[i]; w2[2*i] = v.x; w2[2*i+1] = v.y; }
            __syncthreads();
            for (int t = 0; t < TSEQ; t++) {
                const ull* xp = (const ull*)(xs + t * 64);
                ull a0 = 0, a1 = 0, a2 = 0, a3 = 0;
#pragma unroll
                for (int i = 0; i < 8; i++) {
                    a0 = ffma2(w2[i],      xp[i],      a0);
                    a1 = ffma2(w2[8 + i],  xp[8 + i],  a1);
                    a2 = ffma2(w2[16 + i], xp[16 + i], a2);
                    a3 = ffma2(w2[24 + i], xp[24 + i], a3);
                }
                float2 f0 = unpack2(a0), f1 = unpack2(a1), f2 = unpack2(a2), f3 = unpack2(a3);
                gi[t * G3 + tid] = bg + ((f0.x + f0.y) + (f1.x + f1.y))
                                      + ((f2.x + f2.y) + (f3.x + f3.y));
            }
        }
    } else {
        // prefetch precomputed gi with hi-MLP coalesced float4
        const float4* src = (const float4*)(GI + (size_t)b * TSEQ * G3);
        float4* dst = (float4*)gi;
        for (int i = tid; i < TSEQ * 48; i += 192) dst[i] = src[i];
    }

    // Whh row -> regs (16 independent 16B loads, hi-MLP)
    {
        const ulonglong2* wp = (const ulonglong2*)(Whh + ((size_t)s * G3 + tid) * 64);
#pragma unroll
        for (int i = 0; i < 16; i++) { ulonglong2 v = wp[i]; w2[2*i] = v.x; w2[2*i+1] = v.y; }
    }
    float bh = bhh[s * G3 + tid];
    if (tid < 64) h[tid] = 0.f;
    __syncthreads();

    for (int t = 0; t < TSEQ; t++) {
        const ull* hp = (const ull*)h;
        ull a0 = 0, a1 = 0, a2 = 0, a3 = 0;
#pragma unroll
        for (int i = 0; i < 8; i++) {
            a0 = ffma2(w2[i],      hp[i],      a0);
            a1 = ffma2(w2[8 + i],  hp[8 + i],  a1);
            a2 = ffma2(w2[16 + i], hp[16 + i], a2);
            a3 = ffma2(w2[24 + i], hp[24 + i], a3);
        }
        float2 f0 = unpack2(a0), f1 = unpack2(a1), f2 = unpack2(a2), f3 = unpack2(a3);
        gh[tid] = bh + ((f0.x + f0.y) + (f1.x + f1.y)) + ((f2.x + f2.y) + (f3.x + f3.y));
        __syncthreads();
        if (tid < 64) {
            const float* gt = gi + t * G3;
            float r = sigm(gt[tid] + gh[tid]);
            float z = sigm(gt[64 + tid] + gh[64 + tid]);
            float n = tanhf(gt[128 + tid] + r * gh[128 + tid]);
            float hn = (1.f - z) * n + z * h[tid];
            h[tid] = hn;
            outs[t * 64 + tid] = hn;
        }
        __syncthreads();
    }

    // attention pool:  score_t = tanh(outs_t @ Wa) . h_last   (Wa now in smem)
    int warp = tid >> 5, lane = tid & 31;
    for (int t = warp; t < TSEQ; t += 6) {
        float q1 = 0.f, q2 = 0.f;
#pragma unroll 4
        for (int i = 0; i < 64; i++) {
            float o = outs[t * 64 + i];
            q1 += o * wa[i * 64 + lane];
            q2 += o * wa[i * 64 + lane + 32];
        }
        float sc = tanhf(q1) * h[lane] + tanhf(q2) * h[lane + 32];
#pragma unroll
        for (int off = 16; off > 0; off >>= 1)
            sc += __shfl_xor_sync(0xffffffffu, sc, off);
        if (lane == 0) score[t] = sc;
    }
    __syncthreads();
    if (tid < 32) {
        float v = (tid < TSEQ) ? score[tid] : -1e30f;
        float m = v;
#pragma unroll
        for (int off = 16; off > 0; off >>= 1)
            m = fmaxf(m, __shfl_xor_sync(0xffffffffu, m, off));
        float e = (tid < TSEQ) ? expf(v - m) : 0.f;
        float ss = e;
#pragma unroll
        for (int off = 16; off > 0; off >>= 1)
            ss += __shfl_xor_sync(0xffffffffu, ss, off);
        att[tid] = e / ss;
    }
    __syncthreads();
    if (tid < 64) {
        float a = 0.f;
#pragma unroll 2
        for (int t = 0; t < TSEQ; t++) a += att[t] * outs[t * 64 + tid];
        outv[(size_t)b * 64 + tid] = a;
    }
}

// Fat kernel: text GRU (blocks 0..1999) + price GRU (blocks 2000..2099).
// Price GRU is independent of text_gi -> its latency fully hides.
__global__ void __launch_bounds__(192) gru_text_price_kernel(
    const float* __restrict__ price,
    const float* __restrict__ tg_Whh, const float* __restrict__ tg_bhh,
    const float* __restrict__ ta_W,
    const float* __restrict__ pg_Wih, const float* __restrict__ pg_Whh,
    const float* __restrict__ pg_bih, const float* __restrict__ pg_bhh,
    const float* __restrict__ pa_W)
{
    __shared__ __align__(16) char sm[48384];
    int b = blockIdx.x;
    if (b < NS * DDAYS) {
        gru_body<TTXT, 0>(b / DDAYS, b, nullptr, g_gi_text,
                          nullptr, tg_Whh, nullptr, tg_bhh, ta_W, g_news, sm);
    } else {
        int s = b - NS * DDAYS;
        gru_body<DDAYS, FPRC>(s, s, price, nullptr,
                              pg_Wih, pg_Whh, pg_bih, pg_bhh, pa_W, g_price_vec, sm);
    }
}

__global__ void __launch_bounds__(192) gru_day_kernel(
    const float* __restrict__ sg_Wih, const float* __restrict__ sg_Whh,
    const float* __restrict__ sg_bih, const float* __restrict__ sg_bhh,
    const float* __restrict__ sa_W)
{
    __shared__ __align__(16) char sm[43264];
    int b = blockIdx.x;
    gru_body<DDAYS, HH>(b, b, g_news, nullptr,
                        sg_Wih, sg_Whh, sg_bih, sg_bhh, sa_W, g_text_vec, sm);
}

// =====================================================================
// Bilinear fusion: feature[s,o] = tanh( sum_ij text[i] B[s,o,i,j] price[j] + b )
// grid = NS*8, one warp per output row o (8 rows/block) -> 800 CTAs of
// coalesced float2 streaming, 100MB read bandwidth-bound.
// =====================================================================
__global__ void __launch_bounds__(256) bilinear_kernel(
    const float* __restrict__ B, const float* __restrict__ bb)
{
    __shared__ float pr_s[64], tx_s[64];
    int blk = blockIdx.x;
    int sidx = blk >> 3, og = blk & 7;
    int tid = threadIdx.x;
    if (tid < 64) pr_s[tid] = g_price_vec[sidx * 64 + tid];
    else if (tid < 128) tx_s[tid - 64] = g_text_vec[sidx * 64 + tid - 64];
    __syncthreads();
    int o = og * 8 + (tid >> 5), lane = tid & 31;
    float p0 = pr_s[lane * 2], p1 = pr_s[lane * 2 + 1];
    const float2* Bp = (const float2*)(B + (((size_t)sidx * 64 + o) * 64) * 64) + lane;
    float acc = 0.f;
#pragma unroll 4
    for (int i = 0; i < 64; i++) {
        float2 v = Bp[i * 32];
        acc += tx_s[i] * (v.x * p0 + v.y * p1);
    }
#pragma unroll
    for (int off = 16; off > 0; off >>= 1)
        acc += __shfl_xor_sync(0xffffffffu, acc, off);
    if (lane == 0) g_feature[sidx * 64 + o] = tanhf(acc + bb[sidx * 64 + o]);
}

// =====================================================================
// GAT heads (8 blocks, one per head): masked-softmax attention, elu, concat.
// =====================================================================
__global__ void __launch_bounds__(256) gat_head_kernel(
    const float* __restrict__ gatW, const float* __restrict__ gatA,
    const float* __restrict__ adj)
{
    __shared__ float hh[NS * 64];
    __shared__ float f1[NS], f2[NS];
    __shared__ float attrow[8][NS];
    int head = blockIdx.x;
    int tid = threadIdx.x;
    const float* W = gatW + head * 64 * 64;
    const float* a = gatA + head * 128;
    for (int idx = tid; idx < NS * 64; idx += 256) {
        int i = idx >> 6, k = idx & 63;
        float acc = 0.f;
        const float* xr = g_feature + i * 64;
        for (int m = 0; m < 64; m++) acc += xr[m] * W[m * 64 + k];
        hh[idx] = acc;
    }
    __syncthreads();
    if (tid < NS) {
        float s1 = 0.f, s2 = 0.f;
        for (int k = 0; k < 64; k++) {
            float hv = hh[tid * 64 + k];
            s1 += hv * a[k];
            s2 += hv * a[64 + k];
        }
        f1[tid] = s1; f2[tid] = s2;
    }
    __syncthreads();
    int warp = tid >> 5, lane = tid & 31;
    for (int i = warp; i < NS; i += 8) {
        float fi = f1[i];
        float m = -1e30f;
        for (int j = lane; j < NS; j += 32) {
            float e = fi + f2[j];
            e = (e > 0.f) ? e : 0.2f * e;
            e = (adj[i * NS + j] > 0.f) ? e : -9e15f;
            attrow[warp][j] = e;
            m = fmaxf(m, e);
        }
#pragma unroll
        for (int off = 16; off > 0; off >>= 1)
            m = fmaxf(m, __shfl_xor_sync(0xffffffffu, m, off));
        float ss = 0.f;
        for (int j = lane; j < NS; j += 32) {
            float w = expf(attrow[warp][j] - m);
            attrow[warp][j] = w;
            ss += w;
        }
#pragma unroll
        for (int off = 16; off > 0; off >>= 1)
            ss += __shfl_xor_sync(0xffffffffu, ss, off);
        float inv = 1.f / ss;
        for (int k = lane; k < 64; k += 32) {
            float acc = 0.f;
            for (int j = 0; j < NS; j++) acc += attrow[warp][j] * hh[j * 64 + k];
            float v = acc * inv;
            v = (v > 0.f) ? v : expm1f(v);               // elu
            g_xcat[i * (NHEADS * 64) + head * 64 + k] = v;
        }
    }
}

// =====================================================================
// Final: output GAT layer + blend + double softmax + loss. Single block.
// =====================================================================
__global__ void __launch_bounds__(256) final_kernel(
    const float* __restrict__ outW, const float* __restrict__ outA,
    const float* __restrict__ blW, const float* __restrict__ blb,
    const float* __restrict__ adj, const int* __restrict__ label,
    float* __restrict__ dout, int out_size)
{
    __shared__ float h2[2 * NS];
    __shared__ float o1[2 * NS];
    __shared__ float f1[NS], f2[NS];
    __shared__ float lp[NS];
    int tid = threadIdx.x;
    if (tid < 2 * NS) {
        int i = tid >> 1, c = tid & 1;
        float acc = 0.f;
        const float* xr = g_xcat + i * (NHEADS * 64);
        for (int m = 0; m < NHEADS * 64; m++) acc += xr[m] * outW[m * 2 + c];
        h2[tid] = acc;
        float a2 = blb[c];
        const float* fr = g_feature + i * 64;
        for (int k = 0; k < 64; k++) a2 += fr[k] * blW[k * 2 + c];
        o1[tid] = tanhf(a2);
    }
    __syncthreads();
    if (tid < NS) {
        f1[tid] = h2[2 * tid] * outA[0] + h2[2 * tid + 1] * outA[1];
        f2[tid] = h2[2 * tid] * outA[2] + h2[2 * tid + 1] * outA[3];
    }
    __syncthreads();
    int warp = tid >> 5, lane = tid & 31;
    for (int i = warp; i < NS; i += 8) {
        float fi = f1[i];
        float m = -1e30f;
        for (int j = lane; j < NS; j += 32) {
            float e = fi + f2[j];
            e = (e > 0.f) ? e : 0.2f * e;
            e = (adj[i * NS + j] > 0.f) ? e : -9e15f;
            m = fmaxf(m, e);
        }
#pragma unroll
        for (int off = 16; off > 0; off >>= 1)
            m = fmaxf(m, __shfl_xor_sync(0xffffffffu, m, off));
        float ss = 0.f, a0 = 0.f, a1 = 0.f;
        for (int j = lane; j < NS; j += 32) {
            float e = fi + f2[j];
            e = (e > 0.f) ? e : 0.2f * e;
            e = (adj[i * NS + j] > 0.f) ? e : -9e15f;
            float w = expf(e - m);
            ss += w; a0 += w * h2[2 * j]; a1 += w * h2[2 * j + 1];
        }
#pragma unroll
        for (int off = 16; off > 0; off >>= 1) {
            ss += __shfl_xor_sync(0xffffffffu, ss, off);
            a0 += __shfl_xor_sync(0xffffffffu, a0, off);
            a1 += __shfl_xor_sync(0xffffffffu, a1, off);
        }
        if (lane == 0) {
            float x0 = a0 / ss, x1 = a1 / ss;
            x0 = (x0 > 0.f) ? x0 : expm1f(x0);           // elu
            x1 = (x1 > 0.f) ? x1 : expm1f(x1);
            float v0 = x0 + o1[2 * i], v1 = x1 + o1[2 * i + 1];
            float mm = fmaxf(v0, v1);
            float e0 = expf(v0 - mm), e1 = expf(v1 - mm);
            float inv = 1.f / (e0 + e1);
            float p0 = e0 * inv, p1 = e1 * inv;
            int base = (out_size > 2 * NS) ? 1 : 0;
            dout[base + 2 * i] = p0;
            dout[base + 2 * i + 1] = p1;
            // loss on already-softmaxed output (double-softmax bug preserved)
            float mm2 = fmaxf(p0, p1);
            float lse = mm2 + logf(expf(p0 - mm2) + expf(p1 - mm2));
            int lb = label[i];
            lp[i] = ((lb != 0) ? p1 : p0) - lse;
        }
    }
    __syncthreads();
    if (tid == 0 && out_size > 2 * NS) {
        float sum = 0.f;
        for (int i = 0; i < NS; i++) sum += lp[i];       // deterministic order
        dout[0] = -sum / NS;
    }
}

// =====================================================================
extern "C" void kernel_launch(void* const* d_in, const int* in_sizes, int n_in,
                              void* d_out, int out_size)
{
    // dict order: text, price, label, adj, train, then 23 weight arrays.
    int o = n_in - 23;  // index of pg_Wih (handles train-scalar presence)
    const float* text   = (const float*)d_in[0];
    const float* price  = (const float*)d_in[1];
    const int*   label  = (const int*)d_in[2];
    const float* adj    = (const float*)d_in[3];
    const float* pg_Wih = (const float*)d_in[o + 0];
    const float* pg_Whh = (const float*)d_in[o + 1];
    const float* pg_bih = (const float*)d_in[o + 2];
    const float* pg_bhh = (const float*)d_in[o + 3];
    const float* pa_W   = (const float*)d_in[o + 4];
    const float* tg_Wih = (const float*)d_in[o + 5];
    const float* tg_Whh = (const float*)d_in[o + 6];
    const float* tg_bih = (const float*)d_in[o + 7];
    const float* tg_bhh = (const float*)d_in[o + 8];
    const float* ta_W   = (const float*)d_in[o + 9];
    const float* sg_Wih = (const float*)d_in[o + 10];
    const float* sg_Whh = (const float*)d_in[o + 11];
    const float* sg_bih = (const float*)d_in[o + 12];
    const float* sg_bhh = (const float*)d_in[o + 13];
    const float* sa_W   = (const float*)d_in[o + 14];
    const float* bil_B  = (const float*)d_in[o + 15];
    const float* bil_b  = (const float*)d_in[o + 16];
    const float* bl_W   = (const float*)d_in[o + 17];
    const float* bl_b   = (const float*)d_in[o + 18];
    const float* gat_W  = (const float*)d_in[o + 19];
    const float* gat_a  = (const float*)d_in[o + 20];
    const float* out_W  = (const float*)d_in[o + 21];
    const float* out_a  = (const float*)d_in[o + 22];
    (void)in_sizes;

    // A: text input projections (FFMA2)                      [2000 blocks]
    text_gi_kernel<<<NS * DDAYS, 192>>>(text, tg_Wih, tg_bih);
    // B: text GRU + pool -> news, fused with price GRU       [2100 blocks]
    gru_text_price_kernel<<<NS * DDAYS + NS, 192>>>(
        price, tg_Whh, tg_bhh, ta_W, pg_Wih, pg_Whh, pg_bih, pg_bhh, pa_W);
    // D: day-sequence GRU over news -> text_vec              [100 blocks]
    gru_day_kernel<<<NS, 192>>>(sg_Wih, sg_Whh, sg_bih, sg_bhh, sa_W);
    // E: bilinear fusion -> feature                          [800 blocks]
    bilinear_kernel<<<NS * 8, 256>>>(bil_B, bil_b);
    // F1: 8 GAT heads -> concat
    gat_head_kernel<<<NHEADS, 256>>>(gat_W, gat_a, adj);
    // F2: output GAT layer + blend + softmax + loss
    final_kernel<<<1, 256>>>(out_W, out_a, bl_W, bl_b, adj, label,
                             (float*)d_out, out_size);
}

// round 6
// speedup vs baseline: 1.2827x; 1.1042x over previous
#include <cuda_runtime.h>
#include <math.h>

#define NS    100   // stocks
#define DDAYS 20    // days
#define TTXT  30    // texts per day
#define HH    64    // hidden
#define G3    192   // 3*H
#define NHEADS 8
#define FTXT  512
#define FPRC  3

// ---------------- scratch (device globals; no allocation allowed) ----------------
__device__ float g_gi_text[(size_t)NS * DDAYS * TTXT * G3];   // 11.52M floats
__device__ float g_news[NS * DDAYS * HH];
__device__ float g_price_vec[NS * HH];
__device__ float g_text_vec[NS * HH];
__device__ float g_feature[NS * HH];
__device__ float g_xcat[NS * NHEADS * HH];
// transposed weights: WT[s][k][g]  (coalesced per-thread weight loads)
__device__ float g_WT_tgih[(size_t)NS * FTXT * G3];   // 9.83M
__device__ float g_WT_tghh[(size_t)NS * HH * G3];
__device__ float g_WT_sgih[(size_t)NS * HH * G3];
__device__ float g_WT_sghh[(size_t)NS * HH * G3];
__device__ float g_WT_pghh[(size_t)NS * HH * G3];

typedef unsigned long long ull;

// packed fp32x2 FMA (Blackwell FFMA2; PTX-only, exact fp32 semantics)
__device__ __forceinline__ ull ffma2(ull a, ull b, ull c) {
    ull d;
    asm("fma.rn.f32x2 %0, %1, %2, %3;" : "=l"(d) : "l"(a), "l"(b), "l"(c));
    return d;
}
__device__ __forceinline__ float2 unpack2(ull v) {
    float2 r;
    asm("mov.b64 {%0, %1}, %2;" : "=f"(r.x), "=f"(r.y) : "l"(v));
    return r;
}
__device__ __forceinline__ ull pack2f(float lo, float hi) {
    ull r;
    asm("mov.b64 %0, {%1, %2};" : "=l"(r) : "f"(lo), "f"(hi));
    return r;
}
__device__ __forceinline__ float sigm(float x) { return 1.f / (1.f + expf(-x)); }

// =====================================================================
// Weight transpose: in[s][192][C] -> out[s][C][192], classic smem tile.
// grid (C/32, 6, NS), block (32, 8).
// =====================================================================
template <int C>
__global__ void __launch_bounds__(256) transpose_kernel(
    const float* __restrict__ in, float* __restrict__ out)
{
    __shared__ float tile[32][33];
    int s  = blockIdx.z;
    int c0 = blockIdx.x * 32, r0 = blockIdx.y * 32;
    const float* src = in + ((size_t)s * G3 + r0) * C + c0;
    for (int rr = threadIdx.y; rr < 32; rr += 8)
        tile[rr][threadIdx.x] = src[rr * C + threadIdx.x];
    __syncthreads();
    float* dst = out + ((size_t)s * C + c0) * G3 + r0;
    for (int cc = threadIdx.y; cc < 32; cc += 8)
        dst[cc * G3 + threadIdx.x] = tile[threadIdx.x][cc];
}

// =====================================================================
// Kernel A: text-GRU input projection
//   gi[s,d,t,g] = text[s,d,t,:] . tg_Wih[s,g,:] + tg_bih[s,g]
// One block per (s,d); 192 threads (one per gate row g).
// W read COALESCED from the transposed copy (32 scalar LDG/tile, 1 line
// per warp-instr); x tile [t][kk] in smem, ull2 broadcast reads; FFMA2
// packs k-pairs (2 MACs/slot).
// =====================================================================
__global__ void __launch_bounds__(192) text_gi_kernel(
    const float* __restrict__ X, const float* __restrict__ bih)
{
    __shared__ __align__(16) float xt[TTXT * 32];   // [t][kk]
    int b = blockIdx.x;           // s*DDAYS + d
    int s = b / DDAYS;
    int g = threadIdx.x;
    const float* xg = X + (size_t)b * TTXT * FTXT;
    const float* wtg = g_WT_tgih + (size_t)s * FTXT * G3 + g;

    ull acc2[TTXT];
#pragma unroll
    for (int t = 0; t < TTXT; t++) acc2[t] = 0ull;

    for (int k0 = 0; k0 < FTXT; k0 += 32) {
        __syncthreads();
#pragma unroll
        for (int n = 0; n < 5; n++) {
            int idx = threadIdx.x + n * 192;
            int t = idx >> 5, kk = idx & 31;
            xt[t * 32 + kk] = xg[t * FTXT + k0 + kk];   // coalesced, conflict-free
        }
        __syncthreads();
        // coalesced W^T loads: wt[(k0+j)*192 + g]
        const float* wt = wtg + (size_t)k0 * G3;
        ull wk[16];
#pragma unroll
        for (int j = 0; j < 16; j++)
            wk[j] = pack2f(wt[(2 * j) * G3], wt[(2 * j + 1) * G3]);
#pragma unroll
        for (int t = 0; t < TTXT; t++) {
            const ulonglong2* xr = (const ulonglong2*)(xt + t * 32);  // broadcast
            ull a = acc2[t];
#pragma unroll
            for (int i = 0; i < 8; i++) {
                ulonglong2 xv = xr[i];
                a = ffma2(wk[2*i],     xv.x, a);
                a = ffma2(wk[2*i + 1], xv.y, a);
            }
            acc2[t] = a;
        }
    }
    float bg = bih[s * G3 + g];
    float* out = g_gi_text + (size_t)b * TTXT * G3;
#pragma unroll
    for (int t = 0; t < TTXT; t++) {
        float2 v = unpack2(acc2[t]);
        out[t * G3 + g] = v.x + v.y + bg;
    }
}

// =====================================================================
// Generic GRU stage + attention pooling (torch GRU semantics, h0=0).
// 192 threads. Whh (and Wih for FIN=64) loaded COALESCED from transposed
// copies into per-thread packed registers. Wa/gi prefetched into smem.
// =====================================================================
template <int TSEQ, int FIN>
__device__ __forceinline__ void gru_body(
    int s, int b,
    const float* __restrict__ X, const float* __restrict__ GI,
    const float* __restrict__ Wih,      // FIN==3 only (direct)
    const float* __restrict__ WTih,     // FIN==64 (transposed)
    const float* __restrict__ WThh,     // transposed
    const float* __restrict__ bih, const float* __restrict__ bhh,
    const float* __restrict__ WaG, float* __restrict__ outv, char* smraw)
{
    float* gi    = (float*)smraw;         // TSEQ*192
    float* outs  = gi + TSEQ * G3;        // TSEQ*64
    float* wa    = outs + TSEQ * HH;      // 4096
    float* h     = wa + 4096;             // 64
    float* gh    = h + 64;                // 192
    float* score = gh + G3;               // 32
    float* att   = score + 32;            // 32
    float* xs    = att + 32;              // TSEQ*FIN (FIN>0 only)
    int tid = threadIdx.x;

    // prefetch Wa (needed only at the end; latency hidden behind recurrence)
    {
        const float4* src = (const float4*)(WaG + (size_t)s * 4096);
        float4* dst = (float4*)wa;
        for (int i = tid; i < 1024; i += 192) dst[i] = src[i];
    }

    ull w2[32];

    if (FIN > 0) {
        if (FIN == 3) {
            for (int i = tid; i < TSEQ * 3; i += 192) xs[i] = X[(size_t)b * TSEQ * 3 + i];
        } else {
            const float4* src = (const float4*)(X + (size_t)b * TSEQ * FIN);
            float4* dst = (float4*)xs;
            for (int i = tid; i < TSEQ * FIN / 4; i += 192) dst[i] = src[i];
        }
        float bg = bih[s * G3 + tid];
        if (FIN == 3) {
            const float* wr = Wih + ((size_t)s * G3 + tid) * 3;
            float wi0 = wr[0], wi1 = wr[1], wi2 = wr[2];
            __syncthreads();
            for (int t = 0; t < TSEQ; t++)
                gi[t * G3 + tid] = bg + wi0 * xs[t*3] + wi1 * xs[t*3+1] + wi2 * xs[t*3+2];
        } else {
            const float* wt = WTih + (size_t)s * HH * G3 + tid;   // [k][g] coalesced
#pragma unroll
            for (int j = 0; j < 32; j++)
                w2[j] = pack2f(wt[(2 * j) * G3], wt[(2 * j + 1) * G3]);
            __syncthreads();
            for (int t = 0; t < TSEQ; t++) {
                const ull* xp = (const ull*)(xs + t * 64);
                ull a0 = 0, a1 = 0, a2 = 0, a3 = 0;
#pragma unroll
                for (int i = 0; i < 8; i++) {
                    a0 = ffma2(w2[i],      xp[i],      a0);
                    a1 = ffma2(w2[8 + i],  xp[8 + i],  a1);
                    a2 = ffma2(w2[16 + i], xp[16 + i], a2);
                    a3 = ffma2(w2[24 + i], xp[24 + i], a3);
                }
                float2 f0 = unpack2(a0), f1 = unpack2(a1), f2 = unpack2(a2), f3 = unpack2(a3);
                gi[t * G3 + tid] = bg + ((f0.x + f0.y) + (f1.x + f1.y))
                                      + ((f2.x + f2.y) + (f3.x + f3.y));
            }
        }
    } else {
        // prefetch precomputed gi with hi-MLP coalesced float4
        const float4* src = (const float4*)(GI + (size_t)b * TSEQ * G3);
        float4* dst = (float4*)gi;
        for (int i = tid; i < TSEQ * 48; i += 192) dst[i] = src[i];
    }

    // Whh row -> packed regs via transposed copy (coalesced scalars)
    {
        const float* wt = WThh + (size_t)s * HH * G3 + tid;
#pragma unroll
        for (int j = 0; j < 32; j++)
            w2[j] = pack2f(wt[(2 * j) * G3], wt[(2 * j + 1) * G3]);
    }
    float bh = bhh[s * G3 + tid];
    if (tid < 64) h[tid] = 0.f;
    __syncthreads();

    for (int t = 0; t < TSEQ; t++) {
        const ull* hp = (const ull*)h;
        ull a0 = 0, a1 = 0, a2 = 0, a3 = 0;
#pragma unroll
        for (int i = 0; i < 8; i++) {
            a0 = ffma2(w2[i],      hp[i],      a0);
            a1 = ffma2(w2[8 + i],  hp[8 + i],  a1);
            a2 = ffma2(w2[16 + i], hp[16 + i], a2);
            a3 = ffma2(w2[24 + i], hp[24 + i], a3);
        }
        float2 f0 = unpack2(a0), f1 = unpack2(a1), f2 = unpack2(a2), f3 = unpack2(a3);
        gh[tid] = bh + ((f0.x + f0.y) + (f1.x + f1.y)) + ((f2.x + f2.y) + (f3.x + f3.y));
        __syncthreads();
        if (tid < 64) {
            const float* gt = gi + t * G3;
            float r = sigm(gt[tid] + gh[tid]);
            float z = sigm(gt[64 + tid] + gh[64 + tid]);
            float n = tanhf(gt[128 + tid] + r * gh[128 + tid]);
            float hn = (1.f - z) * n + z * h[tid];
            h[tid] = hn;
            outs[t * 64 + tid] = hn;
        }
        __syncthreads();
    }

    // attention pool:  score_t = tanh(outs_t @ Wa) . h_last   (Wa in smem)
    int warp = tid >> 5, lane = tid & 31;
    for (int t = warp; t < TSEQ; t += 6) {
        float q1 = 0.f, q2 = 0.f;
#pragma unroll 4
        for (int i = 0; i < 64; i++) {
            float o = outs[t * 64 + i];
            q1 += o * wa[i * 64 + lane];
            q2 += o * wa[i * 64 + lane + 32];
        }
        float sc = tanhf(q1) * h[lane] + tanhf(q2) * h[lane + 32];
#pragma unroll
        for (int off = 16; off > 0; off >>= 1)
            sc += __shfl_xor_sync(0xffffffffu, sc, off);
        if (lane == 0) score[t] = sc;
    }
    __syncthreads();
    if (tid < 32) {
        float v = (tid < TSEQ) ? score[tid] : -1e30f;
        float m = v;
#pragma unroll
        for (int off = 16; off > 0; off >>= 1)
            m = fmaxf(m, __shfl_xor_sync(0xffffffffu, m, off));
        float e = (tid < TSEQ) ? expf(v - m) : 0.f;
        float ss = e;
#pragma unroll
        for (int off = 16; off > 0; off >>= 1)
            ss += __shfl_xor_sync(0xffffffffu, ss, off);
        att[tid] = e / ss;
    }
    __syncthreads();
    if (tid < 64) {
        float a = 0.f;
#pragma unroll 2
        for (int t = 0; t < TSEQ; t++) a += att[t] * outs[t * 64 + tid];
        outv[(size_t)b * 64 + tid] = a;
    }
}

// Fat kernel: text GRU (blocks 0..1999) + price GRU (blocks 2000..2099).
__global__ void __launch_bounds__(192) gru_text_price_kernel(
    const float* __restrict__ price,
    const float* __restrict__ tg_bhh, const float* __restrict__ ta_W,
    const float* __restrict__ pg_Wih,
    const float* __restrict__ pg_bih, const float* __restrict__ pg_bhh,
    const float* __restrict__ pa_W)
{
    __shared__ __align__(16) char sm[48384];
    int b = blockIdx.x;
    if (b < NS * DDAYS) {
        gru_body<TTXT, 0>(b / DDAYS, b, nullptr, g_gi_text,
                          nullptr, nullptr, g_WT_tghh,
                          nullptr, tg_bhh, ta_W, g_news, sm);
    } else {
        int s = b - NS * DDAYS;
        gru_body<DDAYS, FPRC>(s, s, price, nullptr,
                              pg_Wih, nullptr, g_WT_pghh,
                              pg_bih, pg_bhh, pa_W, g_price_vec, sm);
    }
}

__global__ void __launch_bounds__(192) gru_day_kernel(
    const float* __restrict__ sg_bih, const float* __restrict__ sg_bhh,
    const float* __restrict__ sa_W)
{
    __shared__ __align__(16) char sm[43264];
    int b = blockIdx.x;
    gru_body<DDAYS, HH>(b, b, g_news, nullptr,
                        nullptr, g_WT_sgih, g_WT_sghh,
                        sg_bih, sg_bhh, sa_W, g_text_vec, sm);
}

// =====================================================================
// Bilinear fusion: feature[s,o] = tanh( sum_ij text[i] B[s,o,i,j] price[j] + b )
// =====================================================================
__global__ void __launch_bounds__(256) bilinear_kernel(
    const float* __restrict__ B, const float* __restrict__ bb)
{
    __shared__ float pr_s[64], tx_s[64];
    int blk = blockIdx.x;
    int sidx = blk >> 3, og = blk & 7;
    int tid = threadIdx.x;
    if (tid < 64) pr_s[tid] = g_price_vec[sidx * 64 + tid];
    else if (tid < 128) tx_s[tid - 64] = g_text_vec[sidx * 64 + tid - 64];
    __syncthreads();
    int o = og * 8 + (tid >> 5), lane = tid & 31;
    float p0 = pr_s[lane * 2], p1 = pr_s[lane * 2 + 1];
    const float2* Bp = (const float2*)(B + (((size_t)sidx * 64 + o) * 64) * 64) + lane;
    float acc = 0.f;
#pragma unroll 4
    for (int i = 0; i < 64; i++) {
        float2 v = Bp[i * 32];
        acc += tx_s[i] * (v.x * p0 + v.y * p1);
    }
#pragma unroll
    for (int off = 16; off > 0; off >>= 1)
        acc += __shfl_xor_sync(0xffffffffu, acc, off);
    if (lane == 0) g_feature[sidx * 64 + o] = tanhf(acc + bb[sidx * 64 + o]);
}

// =====================================================================
// GAT heads (8 blocks, one per head): masked-softmax attention, elu, concat.
// =====================================================================
__global__ void __launch_bounds__(256) gat_head_kernel(
    const float* __restrict__ gatW, const float* __restrict__ gatA,
    const float* __restrict__ adj)
{
    __shared__ float hh[NS * 64];
    __shared__ float f1[NS], f2[NS];
    __shared__ float attrow[8][NS];
    int head = blockIdx.x;
    int tid = threadIdx.x;
    const float* W = gatW + head * 64 * 64;
    const float* a = gatA + head * 128;
    for (int idx = tid; idx < NS * 64; idx += 256) {
        int i = idx >> 6, k = idx & 63;
        float acc = 0.f;
        const float* xr = g_feature + i * 64;
        for (int m = 0; m < 64; m++) acc += xr[m] * W[m * 64 + k];
        hh[idx] = acc;
    }
    __syncthreads();
    if (tid < NS) {
        float s1 = 0.f, s2 = 0.f;
        for (int k = 0; k < 64; k++) {
            float hv = hh[tid * 64 + k];
            s1 += hv * a[k];
            s2 += hv * a[64 + k];
        }
        f1[tid] = s1; f2[tid] = s2;
    }
    __syncthreads();
    int warp = tid >> 5, lane = tid & 31;
    for (int i = warp; i < NS; i += 8) {
        float fi = f1[i];
        float m = -1e30f;
        for (int j = lane; j < NS; j += 32) {
            float e = fi + f2[j];
            e = (e > 0.f) ? e : 0.2f * e;
            e = (adj[i * NS + j] > 0.f) ? e : -9e15f;
            attrow[warp][j] = e;
            m = fmaxf(m, e);
        }
#pragma unroll
        for (int off = 16; off > 0; off >>= 1)
            m = fmaxf(m, __shfl_xor_sync(0xffffffffu, m, off));
        float ss = 0.f;
        for (int j = lane; j < NS; j += 32) {
            float w = expf(attrow[warp][j] - m);
            attrow[warp][j] = w;
            ss += w;
        }
#pragma unroll
        for (int off = 16; off > 0; off >>= 1)
            ss += __shfl_xor_sync(0xffffffffu, ss, off);
        float inv = 1.f / ss;
        for (int k = lane; k < 64; k += 32) {
            float acc = 0.f;
            for (int j = 0; j < NS; j++) acc += attrow[warp][j] * hh[j * 64 + k];
            float v = acc * inv;
            v = (v > 0.f) ? v : expm1f(v);               // elu
            g_xcat[i * (NHEADS * 64) + head * 64 + k] = v;
        }
    }
}

// =====================================================================
// Final: output GAT layer + blend + double softmax + loss. Single block.
// =====================================================================
__global__ void __launch_bounds__(256) final_kernel(
    const float* __restrict__ outW, const float* __restrict__ outA,
    const float* __restrict__ blW, const float* __restrict__ blb,
    const float* __restrict__ adj, const int* __restrict__ label,
    float* __restrict__ dout, int out_size)
{
    __shared__ float h2[2 * NS];
    __shared__ float o1[2 * NS];
    __shared__ float f1[NS], f2[NS];
    __shared__ float lp[NS];
    int tid = threadIdx.x;
    if (tid < 2 * NS) {
        int i = tid >> 1, c = tid & 1;
        float acc = 0.f;
        const float* xr = g_xcat + i * (NHEADS * 64);
        for (int m = 0; m < NHEADS * 64; m++) acc += xr[m] * outW[m * 2 + c];
        h2[tid] = acc;
        float a2 = blb[c];
        const float* fr = g_feature + i * 64;
        for (int k = 0; k < 64; k++) a2 += fr[k] * blW[k * 2 + c];
        o1[tid] = tanhf(a2);
    }
    __syncthreads();
    if (tid < NS) {
        f1[tid] = h2[2 * tid] * outA[0] + h2[2 * tid + 1] * outA[1];
        f2[tid] = h2[2 * tid] * outA[2] + h2[2 * tid + 1] * outA[3];
    }
    __syncthreads();
    int warp = tid >> 5, lane = tid & 31;
    for (int i = warp; i < NS; i += 8) {
        float fi = f1[i];
        float m = -1e30f;
        for (int j = lane; j < NS; j += 32) {
            float e = fi + f2[j];
            e = (e > 0.f) ? e : 0.2f * e;
            e = (adj[i * NS + j] > 0.f) ? e : -9e15f;
            m = fmaxf(m, e);
        }
#pragma unroll
        for (int off = 16; off > 0; off >>= 1)
            m = fmaxf(m, __shfl_xor_sync(0xffffffffu, m, off));
        float ss = 0.f, a0 = 0.f, a1 = 0.f;
        for (int j = lane; j < NS; j += 32) {
            float e = fi + f2[j];
            e = (e > 0.f) ? e : 0.2f * e;
            e = (adj[i * NS + j] > 0.f) ? e : -9e15f;
            float w = expf(e - m);
            ss += w; a0 += w * h2[2 * j]; a1 += w * h2[2 * j + 1];
        }
#pragma unroll
        for (int off = 16; off > 0; off >>= 1) {
            ss += __shfl_xor_sync(0xffffffffu, ss, off);
            a0 += __shfl_xor_sync(0xffffffffu, a0, off);
            a1 += __shfl_xor_sync(0xffffffffu, a1, off);
        }
        if (lane == 0) {
            float x0 = a0 / ss, x1 = a1 / ss;
            x0 = (x0 > 0.f) ? x0 : expm1f(x0);           // elu
            x1 = (x1 > 0.f) ? x1 : expm1f(x1);
            float v0 = x0 + o1[2 * i], v1 = x1 + o1[2 * i + 1];
            float mm = fmaxf(v0, v1);
            float e0 = expf(v0 - mm), e1 = expf(v1 - mm);
            float inv = 1.f / (e0 + e1);
            float p0 = e0 * inv, p1 = e1 * inv;
            int base = (out_size > 2 * NS) ? 1 : 0;
            dout[base + 2 * i] = p0;
            dout[base + 2 * i + 1] = p1;
            // loss on already-softmaxed output (double-softmax bug preserved)
            float mm2 = fmaxf(p0, p1);
            float lse = mm2 + logf(expf(p0 - mm2) + expf(p1 - mm2));
            int lb = label[i];
            lp[i] = ((lb != 0) ? p1 : p0) - lse;
        }
    }
    __syncthreads();
    if (tid == 0 && out_size > 2 * NS) {
        float sum = 0.f;
        for (int i = 0; i < NS; i++) sum += lp[i];       // deterministic order
        dout[0] = -sum / NS;
    }
}

// =====================================================================
extern "C" void kernel_launch(void* const* d_in, const int* in_sizes, int n_in,
                              void* d_out, int out_size)
{
    // dict order: text, price, label, adj, train, then 23 weight arrays.
    int o = n_in - 23;  // index of pg_Wih (handles train-scalar presence)
    const float* text   = (const float*)d_in[0];
    const float* price  = (const float*)d_in[1];
    const int*   label  = (const int*)d_in[2];
    const float* adj    = (const float*)d_in[3];
    const float* pg_Wih = (const float*)d_in[o + 0];
    const float* pg_Whh = (const float*)d_in[o + 1];
    const float* pg_bih = (const float*)d_in[o + 2];
    const float* pg_bhh = (const float*)d_in[o + 3];
    const float* pa_W   = (const float*)d_in[o + 4];
    const float* tg_Wih = (const float*)d_in[o + 5];
    const float* tg_Whh = (const float*)d_in[o + 6];
    const float* tg_bih = (const float*)d_in[o + 7];
    const float* tg_bhh = (const float*)d_in[o + 8];
    const float* ta_W   = (const float*)d_in[o + 9];
    const float* sg_Wih = (const float*)d_in[o + 10];
    const float* sg_Whh = (const float*)d_in[o + 11];
    const float* sg_bih = (const float*)d_in[o + 12];
    const float* sg_bhh = (const float*)d_in[o + 13];
    const float* sa_W   = (const float*)d_in[o + 14];
    const float* bil_B  = (const float*)d_in[o + 15];
    const float* bil_b  = (const float*)d_in[o + 16];
    const float* bl_W   = (const float*)d_in[o + 17];
    const float* bl_b   = (const float*)d_in[o + 18];
    const float* gat_W  = (const float*)d_in[o + 19];
    const float* gat_a  = (const float*)d_in[o + 20];
    const float* out_W  = (const float*)d_in[o + 21];
    const float* out_a  = (const float*)d_in[o + 22];
    (void)in_sizes;

    float *wt_tgih, *wt_tghh, *wt_sgih, *wt_sghh, *wt_pghh;
    cudaGetSymbolAddress((void**)&wt_tgih, g_WT_tgih);
    cudaGetSymbolAddress((void**)&wt_tghh, g_WT_tghh);
    cudaGetSymbolAddress((void**)&wt_sgih, g_WT_sgih);
    cudaGetSymbolAddress((void**)&wt_sghh, g_WT_sghh);
    cudaGetSymbolAddress((void**)&wt_pghh, g_WT_pghh);

    // T: weight transposes (coalesced reads thereafter)
    transpose_kernel<FTXT><<<dim3(FTXT/32, 6, NS), dim3(32, 8)>>>(tg_Wih, wt_tgih);
    transpose_kernel<HH>  <<<dim3(2, 6, NS), dim3(32, 8)>>>(tg_Whh, wt_tghh);
    transpose_kernel<HH>  <<<dim3(2, 6, NS), dim3(32, 8)>>>(pg_Whh, wt_pghh);
    transpose_kernel<HH>  <<<dim3(2, 6, NS), dim3(32, 8)>>>(sg_Wih, wt_sgih);
    transpose_kernel<HH>  <<<dim3(2, 6, NS), dim3(32, 8)>>>(sg_Whh, wt_sghh);

    // A: text input projections (FFMA2, coalesced W)         [2000 blocks]
    text_gi_kernel<<<NS * DDAYS, 192>>>(text, tg_bih);
    // B: text GRU + pool -> news, fused with price GRU       [2100 blocks]
    gru_text_price_kernel<<<NS * DDAYS + NS, 192>>>(
        price, tg_bhh, ta_W, pg_Wih, pg_bih, pg_bhh, pa_W);
    // D: day-sequence GRU over news -> text_vec              [100 blocks]
    gru_day_kernel<<<NS, 192>>>(sg_bih, sg_bhh, sa_W);
    // E: bilinear fusion -> feature                          [800 blocks]
    bilinear_kernel<<<NS * 8, 256>>>(bil_B, bil_b);
    // F1: 8 GAT heads -> concat
    gat_head_kernel<<<NHEADS, 256>>>(gat_W, gat_a, adj);
    // F2: output GAT layer + blend + softmax + loss
    final_kernel<<<1, 256>>>(out_W, out_a, bl_W, bl_b, adj, label,
                             (float*)d_out, out_size);
}